// round 2
// baseline (speedup 1.0000x reference)
#include <cuda_runtime.h>

#define CIN   256
#define HD    512
#define NHEAD 4
#define DDIM  128
#define MAXN  100000

// Scratch (device globals: allocation-free per harness rules)
__device__ __align__(16) float g_q[MAXN * HD];
__device__ __align__(16) float g_k[MAXN * HD];
__device__ __align__(16) float g_v[MAXN * HD];
__device__ __align__(16) float g_kvs[NHEAD * DDIM * DDIM];
__device__ __align__(16) float g_ksum[HD];
__device__ float g_sumsq[2];   // [0]=sum q^2, [1]=sum k^2

// ---------------------------------------------------------------------------
__global__ void zero_scratch() {
    const int total = NHEAD * DDIM * DDIM + HD + 2;
    for (int i = blockIdx.x * blockDim.x + threadIdx.x; i < total;
         i += gridDim.x * blockDim.x) {
        if (i < NHEAD * DDIM * DDIM) g_kvs[i] = 0.f;
        else if (i < NHEAD * DDIM * DDIM + HD) g_ksum[i - NHEAD * DDIM * DDIM] = 0.f;
        else g_sumsq[i - NHEAD * DDIM * DDIM - HD] = 0.f;
    }
}

// ---------------------------------------------------------------------------
// C[N,512] = A[N,256] @ W[256,512] + bias.  BM=BN=128, BK=16, 8x8/thread.
__global__ __launch_bounds__(256) void gemm_bias(
    const float* __restrict__ A, const float* __restrict__ W,
    const float* __restrict__ bias, int which, int N)
{
    __shared__ __align__(16) float As[16][128];
    __shared__ __align__(16) float Bs[16][128];
    float* C = (which == 0) ? g_q : (which == 1) ? g_k : g_v;

    const int r0 = blockIdx.x * 128;
    const int c0 = blockIdx.y * 128;
    const int t  = threadIdx.x;
    const int ty = t >> 4, tx = t & 15;

    float acc[8][8];
#pragma unroll
    for (int i = 0; i < 8; i++)
#pragma unroll
        for (int j = 0; j < 8; j++) acc[i][j] = 0.f;

    for (int kk = 0; kk < CIN; kk += 16) {
        // A tile, stored transposed As[k][m]
#pragma unroll
        for (int s = 0; s < 2; s++) {
            int v = t + s * 256;
            int rowA = v >> 2;
            int c4 = (v & 3) << 2;
            int grow = r0 + rowA;
            float4 f = make_float4(0.f, 0.f, 0.f, 0.f);
            if (grow < N)
                f = *reinterpret_cast<const float4*>(A + (size_t)grow * CIN + kk + c4);
            As[c4 + 0][rowA] = f.x;
            As[c4 + 1][rowA] = f.y;
            As[c4 + 2][rowA] = f.z;
            As[c4 + 3][rowA] = f.w;
        }
        // W tile Bs[k][n]
#pragma unroll
        for (int s = 0; s < 2; s++) {
            int v = t + s * 256;
            int rowB = v >> 5;
            int c4 = (v & 31) << 2;
            *reinterpret_cast<float4*>(&Bs[rowB][c4]) =
                *reinterpret_cast<const float4*>(W + (size_t)(kk + rowB) * HD + c0 + c4);
        }
        __syncthreads();
#pragma unroll
        for (int k = 0; k < 16; k++) {
            float a[8], b[8];
            *reinterpret_cast<float4*>(&a[0]) = *reinterpret_cast<float4*>(&As[k][ty * 8]);
            *reinterpret_cast<float4*>(&a[4]) = *reinterpret_cast<float4*>(&As[k][ty * 8 + 4]);
            *reinterpret_cast<float4*>(&b[0]) = *reinterpret_cast<float4*>(&Bs[k][tx * 8]);
            *reinterpret_cast<float4*>(&b[4]) = *reinterpret_cast<float4*>(&Bs[k][tx * 8 + 4]);
#pragma unroll
            for (int i = 0; i < 8; i++)
#pragma unroll
                for (int j = 0; j < 8; j++)
                    acc[i][j] = fmaf(a[i], b[j], acc[i][j]);
        }
        __syncthreads();
    }

    float bseg[8];
    *reinterpret_cast<float4*>(&bseg[0]) = *reinterpret_cast<const float4*>(bias + c0 + tx * 8);
    *reinterpret_cast<float4*>(&bseg[4]) = *reinterpret_cast<const float4*>(bias + c0 + tx * 8 + 4);
#pragma unroll
    for (int i = 0; i < 8; i++) {
        int row = r0 + ty * 8 + i;
        if (row < N) {
            float4 o0 = make_float4(acc[i][0] + bseg[0], acc[i][1] + bseg[1],
                                    acc[i][2] + bseg[2], acc[i][3] + bseg[3]);
            float4 o1 = make_float4(acc[i][4] + bseg[4], acc[i][5] + bseg[5],
                                    acc[i][6] + bseg[6], acc[i][7] + bseg[7]);
            *reinterpret_cast<float4*>(C + (size_t)row * HD + c0 + tx * 8)     = o0;
            *reinterpret_cast<float4*>(C + (size_t)row * HD + c0 + tx * 8 + 4) = o1;
        }
    }
}

// ---------------------------------------------------------------------------
// Column sums of k (ks_sum) + global sum-of-squares of q and k.
__global__ __launch_bounds__(256) void stats_kernel(int N)
{
    const int t = threadIdx.x;
    float ks0 = 0.f, ks1 = 0.f, sq_q = 0.f, sq_k = 0.f;
    for (int row = blockIdx.x; row < N; row += gridDim.x) {
        const float* kr = g_k + (size_t)row * HD;
        const float* qr = g_q + (size_t)row * HD;
        float k0 = kr[t], k1 = kr[t + 256];
        float q0 = qr[t], q1 = qr[t + 256];
        ks0 += k0; ks1 += k1;
        sq_k = fmaf(k0, k0, sq_k); sq_k = fmaf(k1, k1, sq_k);
        sq_q = fmaf(q0, q0, sq_q); sq_q = fmaf(q1, q1, sq_q);
    }
    atomicAdd(&g_ksum[t], ks0);
    atomicAdd(&g_ksum[t + 256], ks1);

    __shared__ float2 red[256];
    red[t] = make_float2(sq_q, sq_k);
    __syncthreads();
    for (int s = 128; s > 0; s >>= 1) {
        if (t < s) { red[t].x += red[t + s].x; red[t].y += red[t + s].y; }
        __syncthreads();
    }
    if (t == 0) {
        atomicAdd(&g_sumsq[0], red[0].x);
        atomicAdd(&g_sumsq[1], red[0].y);
    }
}

// ---------------------------------------------------------------------------
// kvs[h,m,d] += sum_n k[n,h,m] * v[n,h,d]   (split-K over N, atomicAdd)
__global__ __launch_bounds__(256) void kvs_kernel(int N)
{
    __shared__ __align__(16) float Ks[16][128];
    __shared__ __align__(16) float Vs[16][128];
    const int h = blockIdx.y;
    const int nchunks = gridDim.x;
    const int chunk = (N + nchunks - 1) / nchunks;
    const int n0 = blockIdx.x * chunk;
    const int n1 = min(n0 + chunk, N);
    const int t = threadIdx.x;
    const int ty = t >> 4, tx = t & 15;

    float acc[8][8];
#pragma unroll
    for (int i = 0; i < 8; i++)
#pragma unroll
        for (int j = 0; j < 8; j++) acc[i][j] = 0.f;

    for (int nn = n0; nn < n1; nn += 16) {
#pragma unroll
        for (int s = 0; s < 2; s++) {
            int v = t + s * 256;
            int r = v >> 5;
            int c4 = (v & 31) << 2;
            int grow = nn + r;
            float4 fk = make_float4(0.f, 0.f, 0.f, 0.f);
            float4 fv = fk;
            if (grow < n1) {
                fk = *reinterpret_cast<const float4*>(g_k + (size_t)grow * HD + h * DDIM + c4);
                fv = *reinterpret_cast<const float4*>(g_v + (size_t)grow * HD + h * DDIM + c4);
            }
            *reinterpret_cast<float4*>(&Ks[r][c4]) = fk;
            *reinterpret_cast<float4*>(&Vs[r][c4]) = fv;
        }
        __syncthreads();
#pragma unroll
        for (int k = 0; k < 16; k++) {
            float a[8], b[8];
            *reinterpret_cast<float4*>(&a[0]) = *reinterpret_cast<float4*>(&Ks[k][ty * 8]);
            *reinterpret_cast<float4*>(&a[4]) = *reinterpret_cast<float4*>(&Ks[k][ty * 8 + 4]);
            *reinterpret_cast<float4*>(&b[0]) = *reinterpret_cast<float4*>(&Vs[k][tx * 8]);
            *reinterpret_cast<float4*>(&b[4]) = *reinterpret_cast<float4*>(&Vs[k][tx * 8 + 4]);
#pragma unroll
            for (int i = 0; i < 8; i++)
#pragma unroll
                for (int j = 0; j < 8; j++)
                    acc[i][j] = fmaf(a[i], b[j], acc[i][j]);
        }
        __syncthreads();
    }

    float* dst = g_kvs + h * DDIM * DDIM;
#pragma unroll
    for (int i = 0; i < 8; i++)
#pragma unroll
        for (int j = 0; j < 8; j++)
            atomicAdd(dst + (ty * 8 + i) * DDIM + tx * 8 + j, acc[i][j]);
}

// ---------------------------------------------------------------------------
// out[n,d] = 0.25 * sum_h ( q[n,h,:]·kvs[h,:,d]·inv + N·v[n,h,d] ) * rden[n,h]
// rden = 1/(q[n,h,:]·ksum[h]·inv + N).  rden*inv folded into Q tile at load.
__global__ __launch_bounds__(256) void final_kernel(float* __restrict__ out, int N)
{
    __shared__ __align__(16) float Qs[16][128];
    __shared__ __align__(16) float KVs[16][128];
    __shared__ float rden[128];
    __shared__ float ksum_s[128];

    const int r0 = blockIdx.x * 128;
    const int t  = threadIdx.x;
    const int ty = t >> 4, tx = t & 15;
    const float inv = rsqrtf(g_sumsq[0]) * rsqrtf(g_sumsq[1]);
    const float Nf  = (float)N;

    float oacc[8][8];
#pragma unroll
    for (int i = 0; i < 8; i++)
#pragma unroll
        for (int j = 0; j < 8; j++) oacc[i][j] = 0.f;

    for (int h = 0; h < NHEAD; h++) {
        if (t < 128) ksum_s[t] = g_ksum[h * DDIM + t];
        __syncthreads();
        if (t < 128) {
            int row = r0 + t;
            float d = 0.f;
            if (row < N) {
                const float* qr = g_q + (size_t)row * HD + h * DDIM;
#pragma unroll 8
                for (int m = 0; m < DDIM; m++) d = fmaf(qr[m], ksum_s[m], d);
            }
            rden[t] = 1.0f / (d * inv + Nf);
        }
        __syncthreads();

        for (int kk = 0; kk < DDIM; kk += 16) {
            // Q tile transposed, pre-scaled by rden[row]*inv
#pragma unroll
            for (int s = 0; s < 2; s++) {
                int v = t + s * 256;
                int rowA = v >> 2;
                int c4 = (v & 3) << 2;
                int grow = r0 + rowA;
                float4 f = make_float4(0.f, 0.f, 0.f, 0.f);
                if (grow < N)
                    f = *reinterpret_cast<const float4*>(g_q + (size_t)grow * HD + h * DDIM + kk + c4);
                float sc = rden[rowA] * inv;
                Qs[c4 + 0][rowA] = f.x * sc;
                Qs[c4 + 1][rowA] = f.y * sc;
                Qs[c4 + 2][rowA] = f.z * sc;
                Qs[c4 + 3][rowA] = f.w * sc;
            }
#pragma unroll
            for (int s = 0; s < 2; s++) {
                int v = t + s * 256;
                int r = v >> 5;
                int c4 = (v & 31) << 2;
                *reinterpret_cast<float4*>(&KVs[r][c4]) =
                    *reinterpret_cast<const float4*>(g_kvs + h * DDIM * DDIM + (size_t)(kk + r) * DDIM + c4);
            }
            __syncthreads();
#pragma unroll
            for (int k = 0; k < 16; k++) {
                float a[8], b[8];
                *reinterpret_cast<float4*>(&a[0]) = *reinterpret_cast<float4*>(&Qs[k][ty * 8]);
                *reinterpret_cast<float4*>(&a[4]) = *reinterpret_cast<float4*>(&Qs[k][ty * 8 + 4]);
                *reinterpret_cast<float4*>(&b[0]) = *reinterpret_cast<float4*>(&KVs[k][tx * 8]);
                *reinterpret_cast<float4*>(&b[4]) = *reinterpret_cast<float4*>(&KVs[k][tx * 8 + 4]);
#pragma unroll
                for (int i = 0; i < 8; i++)
#pragma unroll
                    for (int j = 0; j < 8; j++)
                        oacc[i][j] = fmaf(a[i], b[j], oacc[i][j]);
            }
            __syncthreads();
        }

        // + N * v[n,h,d] * rden
#pragma unroll
        for (int i = 0; i < 8; i++) {
            int row = r0 + ty * 8 + i;
            if (row < N) {
                float nrd = Nf * rden[ty * 8 + i];
                const float* vr = g_v + (size_t)row * HD + h * DDIM + tx * 8;
                float4 v0 = *reinterpret_cast<const float4*>(vr);
                float4 v1 = *reinterpret_cast<const float4*>(vr + 4);
                oacc[i][0] = fmaf(nrd, v0.x, oacc[i][0]);
                oacc[i][1] = fmaf(nrd, v0.y, oacc[i][1]);
                oacc[i][2] = fmaf(nrd, v0.z, oacc[i][2]);
                oacc[i][3] = fmaf(nrd, v0.w, oacc[i][3]);
                oacc[i][4] = fmaf(nrd, v1.x, oacc[i][4]);
                oacc[i][5] = fmaf(nrd, v1.y, oacc[i][5]);
                oacc[i][6] = fmaf(nrd, v1.z, oacc[i][6]);
                oacc[i][7] = fmaf(nrd, v1.w, oacc[i][7]);
            }
        }
        __syncthreads();
    }

#pragma unroll
    for (int i = 0; i < 8; i++) {
        int row = r0 + ty * 8 + i;
        if (row < N) {
            float4 o0 = make_float4(0.25f * oacc[i][0], 0.25f * oacc[i][1],
                                    0.25f * oacc[i][2], 0.25f * oacc[i][3]);
            float4 o1 = make_float4(0.25f * oacc[i][4], 0.25f * oacc[i][5],
                                    0.25f * oacc[i][6], 0.25f * oacc[i][7]);
            *reinterpret_cast<float4*>(out + (size_t)row * DDIM + tx * 8)     = o0;
            *reinterpret_cast<float4*>(out + (size_t)row * DDIM + tx * 8 + 4) = o1;
        }
    }
}

// ---------------------------------------------------------------------------
extern "C" void kernel_launch(void* const* d_in, const int* in_sizes, int n_in,
                              void* d_out, int out_size)
{
    const float* q_in = (const float*)d_in[0];
    const float* k_in = (const float*)d_in[1];
    const float* v_in = (const float*)d_in[2];
    const float* Wq   = (const float*)d_in[3];
    const float* bq   = (const float*)d_in[4];
    const float* Wk   = (const float*)d_in[5];
    const float* bk   = (const float*)d_in[6];
    const float* Wv   = (const float*)d_in[7];
    const float* bv   = (const float*)d_in[8];
    float* out = (float*)d_out;

    const int N = in_sizes[0] / CIN;
    const int rowBlocks = (N + 127) / 128;

    zero_scratch<<<64, 256>>>();
    gemm_bias<<<dim3(rowBlocks, 4), 256>>>(q_in, Wq, bq, 0, N);
    gemm_bias<<<dim3(rowBlocks, 4), 256>>>(k_in, Wk, bk, 1, N);
    gemm_bias<<<dim3(rowBlocks, 4), 256>>>(v_in, Wv, bv, 2, N);
    stats_kernel<<<512, 256>>>(N);
    kvs_kernel<<<dim3(128, NHEAD), 256>>>(N);
    final_kernel<<<rowBlocks, 256>>>(out, N);
}

// round 3
// speedup vs baseline: 15.4148x; 15.4148x over previous
#include <cuda_runtime.h>

#define CIN   256
#define HD    512
#define NHEAD 4
#define DDIM  128

// Head-averaged weights/bias (device globals: allocation-free per harness rules)
__device__ __align__(16) float g_Wv_eff[CIN * DDIM];   // [256,128]
__device__ __align__(16) float g_bv_eff[DDIM];

// ---------------------------------------------------------------------------
// W̄v[c,d] = 0.25 * sum_h Wv[c, h*128 + d];  b̄v[d] = 0.25 * sum_h bv[h*128+d]
__global__ void reduce_weights(const float* __restrict__ Wv,
                               const float* __restrict__ bv)
{
    int idx = blockIdx.x * blockDim.x + threadIdx.x;
    if (idx < CIN * DDIM) {
        int c = idx >> 7;          // / 128
        int d = idx & 127;
        float s = 0.f;
#pragma unroll
        for (int h = 0; h < NHEAD; h++) s += Wv[(size_t)c * HD + h * DDIM + d];
        g_Wv_eff[idx] = 0.25f * s;
    }
    if (idx < DDIM) {
        float s = 0.f;
#pragma unroll
        for (int h = 0; h < NHEAD; h++) s += bv[h * DDIM + idx];
        g_bv_eff[idx] = 0.25f * s;
    }
}

// ---------------------------------------------------------------------------
// out[N,128] = A[N,256] @ g_Wv_eff[256,128] + g_bv_eff
// BM=128, BN=128 (full width), BK=16, 8x8 per thread, 256 threads.
__global__ __launch_bounds__(256) void gemm_out(
    const float* __restrict__ A, float* __restrict__ out, int N)
{
    __shared__ __align__(16) float As[16][128];   // transposed: As[k][m]
    __shared__ __align__(16) float Bs[16][128];   // Bs[k][n]

    const int r0 = blockIdx.x * 128;
    const int t  = threadIdx.x;
    const int ty = t >> 4, tx = t & 15;

    float acc[8][8];
#pragma unroll
    for (int i = 0; i < 8; i++)
#pragma unroll
        for (int j = 0; j < 8; j++) acc[i][j] = 0.f;

#pragma unroll 1
    for (int kk = 0; kk < CIN; kk += 16) {
        // A tile: 128 rows x 16 k — each thread 2 float4 loads, store transposed
#pragma unroll
        for (int s = 0; s < 2; s++) {
            int v = t + s * 256;
            int rowA = v >> 2;            // 0..127
            int c4 = (v & 3) << 2;        // 0,4,8,12
            int grow = r0 + rowA;
            float4 f = make_float4(0.f, 0.f, 0.f, 0.f);
            if (grow < N)
                f = *reinterpret_cast<const float4*>(A + (size_t)grow * CIN + kk + c4);
            As[c4 + 0][rowA] = f.x;
            As[c4 + 1][rowA] = f.y;
            As[c4 + 2][rowA] = f.z;
            As[c4 + 3][rowA] = f.w;
        }
        // B tile: 16 k-rows x 128 n
#pragma unroll
        for (int s = 0; s < 2; s++) {
            int v = t + s * 256;
            int rowB = v >> 5;            // 0..15
            int c4 = (v & 31) << 2;       // 0..124
            *reinterpret_cast<float4*>(&Bs[rowB][c4]) =
                *reinterpret_cast<const float4*>(g_Wv_eff + (size_t)(kk + rowB) * DDIM + c4);
        }
        __syncthreads();
#pragma unroll
        for (int k = 0; k < 16; k++) {
            float a[8], b[8];
            *reinterpret_cast<float4*>(&a[0]) = *reinterpret_cast<float4*>(&As[k][ty * 8]);
            *reinterpret_cast<float4*>(&a[4]) = *reinterpret_cast<float4*>(&As[k][ty * 8 + 4]);
            *reinterpret_cast<float4*>(&b[0]) = *reinterpret_cast<float4*>(&Bs[k][tx * 8]);
            *reinterpret_cast<float4*>(&b[4]) = *reinterpret_cast<float4*>(&Bs[k][tx * 8 + 4]);
#pragma unroll
            for (int i = 0; i < 8; i++)
#pragma unroll
                for (int j = 0; j < 8; j++)
                    acc[i][j] = fmaf(a[i], b[j], acc[i][j]);
        }
        __syncthreads();
    }

    float bseg[8];
    *reinterpret_cast<float4*>(&bseg[0]) = *reinterpret_cast<const float4*>(g_bv_eff + tx * 8);
    *reinterpret_cast<float4*>(&bseg[4]) = *reinterpret_cast<const float4*>(g_bv_eff + tx * 8 + 4);

#pragma unroll
    for (int i = 0; i < 8; i++) {
        int row = r0 + ty * 8 + i;
        if (row < N) {
            float4 o0 = make_float4(acc[i][0] + bseg[0], acc[i][1] + bseg[1],
                                    acc[i][2] + bseg[2], acc[i][3] + bseg[3]);
            float4 o1 = make_float4(acc[i][4] + bseg[4], acc[i][5] + bseg[5],
                                    acc[i][6] + bseg[6], acc[i][7] + bseg[7]);
            *reinterpret_cast<float4*>(out + (size_t)row * DDIM + tx * 8)     = o0;
            *reinterpret_cast<float4*>(out + (size_t)row * DDIM + tx * 8 + 4) = o1;
        }
    }
}

// ---------------------------------------------------------------------------
extern "C" void kernel_launch(void* const* d_in, const int* in_sizes, int n_in,
                              void* d_out, int out_size)
{
    const float* v_in = (const float*)d_in[2];
    const float* Wv   = (const float*)d_in[7];
    const float* bv   = (const float*)d_in[8];
    float* out = (float*)d_out;

    const int N = in_sizes[0] / CIN;
    const int rowBlocks = (N + 127) / 128;

    reduce_weights<<<(CIN * DDIM + 255) / 256, 256>>>(Wv, bv);
    gemm_out<<<rowBlocks, 256>>>(v_in, out, N);
}

// round 9
// speedup vs baseline: 30.1162x; 1.9537x over previous
#include <cuda_runtime.h>
#include <cuda_bf16.h>
#include <cstdint>

#define CIN   256
#define HD    512
#define NHEAD 4
#define DDIM  128

// Head-averaged weight, split into bf16 hi/lo, stored [n][k] row-major (B^T)
__device__ __align__(16) unsigned short g_Wt_hi[DDIM * CIN];
__device__ __align__(16) unsigned short g_Wt_lo[DDIM * CIN];
__device__ __align__(16) float g_bias[DDIM];

#define SW128(x) ((x) ^ (((x) >> 3) & 0x70))

// SMEM layout (bytes)
#define SM_BIAS  0
#define SM_A     1024                        // 2 bufs x (hi 16K, lo 16K)
#define SM_B     (1024 + 4 * 16384)          // Bh[128][264], Bl[128][264]
#define BSTRIDE  528
#define BSIZE    (128 * BSTRIDE)
#define SMEM_SZ  (SM_B + 2 * BSIZE)

__device__ __forceinline__ uint32_t smem_u32(const void* p) {
    uint32_t a;
    asm("{ .reg .u64 t; cvta.to.shared.u64 t, %1; cvt.u32.u64 %0, t; }" : "=r"(a) : "l"(p));
    return a;
}
__device__ __forceinline__ void ldmatrix_x4(uint32_t* r, uint32_t addr) {
    asm volatile("ldmatrix.sync.aligned.m8n8.x4.shared.b16 {%0,%1,%2,%3}, [%4];"
                 : "=r"(r[0]), "=r"(r[1]), "=r"(r[2]), "=r"(r[3]) : "r"(addr));
}
__device__ __forceinline__ void mma_bf16(float* c, const uint32_t* a, const uint32_t* b) {
    asm volatile(
        "mma.sync.aligned.m16n8k16.row.col.f32.bf16.bf16.f32 "
        "{%0,%1,%2,%3}, {%4,%5,%6,%7}, {%8,%9}, {%0,%1,%2,%3};"
        : "+f"(c[0]), "+f"(c[1]), "+f"(c[2]), "+f"(c[3])
        : "r"(a[0]), "r"(a[1]), "r"(a[2]), "r"(a[3]), "r"(b[0]), "r"(b[1]));
}

// ---------------------------------------------------------------------------
// Prologue: W̄[k][n] = 0.25*sum_h Wv[k, h*128+n] → bf16 hi/lo at [n][k]; bias.
// ---------------------------------------------------------------------------
__global__ void reduce_weights(const float* __restrict__ Wv, const float* __restrict__ bv)
{
    int idx = blockIdx.x * blockDim.x + threadIdx.x;
    if (idx < DDIM * CIN) {
        int n = idx >> 8;
        int k = idx & 255;
        float s = 0.f;
#pragma unroll
        for (int h = 0; h < NHEAD; h++) s += Wv[(size_t)k * HD + h * DDIM + n];
        float w = 0.25f * s;
        __nv_bfloat16 hh = __float2bfloat16_rn(w);
        float res = w - __bfloat162float(hh);
        __nv_bfloat16 ll = __float2bfloat16_rn(res);
        unsigned short uh, ul;
        memcpy(&uh, &hh, 2); memcpy(&ul, &ll, 2);
        g_Wt_hi[n * CIN + k] = uh;
        g_Wt_lo[n * CIN + k] = ul;
    }
    if (idx < DDIM) {
        float s = 0.f;
#pragma unroll
        for (int h = 0; h < NHEAD; h++) s += bv[h * DDIM + idx];
        g_bias[idx] = 0.25f * s;
    }
}

// ---------------------------------------------------------------------------
// out[N,128] = A[N,256] @ W̄ + bias   (HMMA bf16 3-term split)
// ---------------------------------------------------------------------------
__global__ __launch_bounds__(256, 1) void gemm_hmma(const float* __restrict__ A,
                                                    float* __restrict__ out, int N)
{
    extern __shared__ __align__(1024) char smem[];
    const uint32_t sb = smem_u32(smem);
    const int t = threadIdx.x;
    const int wid = t >> 5, lane = t & 31;
    const int r0 = blockIdx.x * 128;

    const int m0 = (wid & 3) * 32;     // warp row base within CTA tile
    const int n0 = (wid >> 2) * 64;    // warp col base

    // per-lane ldmatrix address components
    const uint32_t mA_local = ((lane >> 3) & 1) * 8 + (lane & 7);
    const uint32_t kA_off   = (lane >> 4) * 16;               // bytes
    const uint32_t nB_local = (lane >> 4) * 8 + (lane & 7);
    const uint32_t kB_off   = ((lane >> 3) & 1) * 16;         // bytes

    // ---- stage bias + full B (hi/lo) into smem ----
    if (t < 128) *reinterpret_cast<float*>(smem + SM_BIAS + t * 4) = g_bias[t];
#pragma unroll
    for (int i = 0; i < 16; i++) {
        int idx = i * 256 + t;            // 0..4095 uint4 units per array
        int row = idx >> 5;               // n
        int u = idx & 31;                 // 16-B unit within 512-B of data
        uint4 vh = *reinterpret_cast<const uint4*>(g_Wt_hi + row * CIN + u * 8);
        uint4 vl = *reinterpret_cast<const uint4*>(g_Wt_lo + row * CIN + u * 8);
        *reinterpret_cast<uint4*>(smem + SM_B + row * BSTRIDE + u * 16) = vh;
        *reinterpret_cast<uint4*>(smem + SM_B + BSIZE + row * BSTRIDE + u * 16) = vl;
    }

    float acc[2][8][4];
#pragma unroll
    for (int mt = 0; mt < 2; mt++)
#pragma unroll
        for (int nt = 0; nt < 8; nt++)
#pragma unroll
            for (int r = 0; r < 4; r++) acc[mt][nt][r] = 0.f;

    float4 pf[8];
    // ---- prefetch chunk 0 ----
#pragma unroll
    for (int it = 0; it < 8; it++) {
        int v = it * 256 + t;
        int row = v >> 4, u = v & 15;
        int grow = r0 + row;
        pf[it] = (grow < N)
            ? *reinterpret_cast<const float4*>(A + (size_t)grow * CIN + u * 4)
            : make_float4(0.f, 0.f, 0.f, 0.f);
    }
    // ---- convert/store chunk 0 into buf 0 ----
    {
        uint32_t ah = sb + SM_A;            // buf0 hi
        uint32_t al = ah + 16384;
#pragma unroll
        for (int it = 0; it < 8; it++) {
            int v = it * 256 + t;
            int row = v >> 4, u = v & 15;
            float4 f = pf[it];
            __nv_bfloat16 h0 = __float2bfloat16_rn(f.x), h1 = __float2bfloat16_rn(f.y);
            __nv_bfloat16 h2 = __float2bfloat16_rn(f.z), h3 = __float2bfloat16_rn(f.w);
            __nv_bfloat16 l0 = __float2bfloat16_rn(f.x - __bfloat162float(h0));
            __nv_bfloat16 l1 = __float2bfloat16_rn(f.y - __bfloat162float(h1));
            __nv_bfloat16 l2 = __float2bfloat16_rn(f.z - __bfloat162float(h2));
            __nv_bfloat16 l3 = __float2bfloat16_rn(f.w - __bfloat162float(h3));
            unsigned short s0, s1, s2, s3, q0, q1, q2, q3;
            memcpy(&s0, &h0, 2); memcpy(&s1, &h1, 2); memcpy(&s2, &h2, 2); memcpy(&s3, &h3, 2);
            memcpy(&q0, &l0, 2); memcpy(&q1, &l1, 2); memcpy(&q2, &l2, 2); memcpy(&q3, &l3, 2);
            uint32_t hx = (uint32_t)s0 | ((uint32_t)s1 << 16);
            uint32_t hy = (uint32_t)s2 | ((uint32_t)s3 << 16);
            uint32_t lx = (uint32_t)q0 | ((uint32_t)q1 << 16);
            uint32_t ly = (uint32_t)q2 | ((uint32_t)q3 << 16);
            uint32_t off = SW128((uint32_t)(row * 128 + u * 8));
            asm volatile("st.shared.v2.b32 [%0], {%1,%2};" :: "r"(ah + off), "r"(hx), "r"(hy) : "memory");
            asm volatile("st.shared.v2.b32 [%0], {%1,%2};" :: "r"(al + off), "r"(lx), "r"(ly) : "memory");
        }
    }
    __syncthreads();

    // ---- main loop over 4 K-chunks of 64 ----
#pragma unroll 1
    for (int c = 0; c < 4; c++) {
        const int buf = c & 1;
        // prefetch next chunk while MMAs run
        if (c < 3) {
#pragma unroll
            for (int it = 0; it < 8; it++) {
                int v = it * 256 + t;
                int row = v >> 4, u = v & 15;
                int grow = r0 + row;
                pf[it] = (grow < N)
                    ? *reinterpret_cast<const float4*>(A + (size_t)grow * CIN + (c + 1) * 64 + u * 4)
                    : make_float4(0.f, 0.f, 0.f, 0.f);
            }
        }

        const uint32_t abh = sb + SM_A + buf * 32768;          // A hi
        const uint32_t abl = abh + 16384;                      // A lo
#pragma unroll 1
        for (int split = 0; split < 3; split++) {
            const uint32_t abase = (split == 2) ? abl : abh;
            const uint32_t bbase = sb + SM_B + ((split == 1) ? BSIZE : 0);
#pragma unroll
            for (int k16 = 0; k16 < 4; k16++) {
                uint32_t a[2][4];
#pragma unroll
                for (int mt = 0; mt < 2; mt++) {
                    uint32_t row = m0 + mt * 16 + mA_local;
                    uint32_t off = SW128(row * 128 + (uint32_t)k16 * 32 + kA_off);
                    ldmatrix_x4(a[mt], abase + off);
                }
                uint32_t b[8][2];
#pragma unroll
                for (int nq = 0; nq < 4; nq++) {
                    uint32_t r[4];
                    uint32_t nrow = n0 + nq * 16 + nB_local;
                    uint32_t addr = bbase + nrow * BSTRIDE + (uint32_t)c * 128 + (uint32_t)k16 * 32 + kB_off;
                    ldmatrix_x4(r, addr);
                    b[nq * 2 + 0][0] = r[0]; b[nq * 2 + 0][1] = r[1];
                    b[nq * 2 + 1][0] = r[2]; b[nq * 2 + 1][1] = r[3];
                }
#pragma unroll
                for (int mt = 0; mt < 2; mt++)
#pragma unroll
                    for (int nt = 0; nt < 8; nt++)
                        mma_bf16(acc[mt][nt], a[mt], b[nt]);
            }
        }

        // convert + store prefetched chunk into the other buffer
        if (c < 3) {
            uint32_t ah = sb + SM_A + ((c + 1) & 1) * 32768;
            uint32_t al = ah + 16384;
#pragma unroll
            for (int it = 0; it < 8; it++) {
                int v = it * 256 + t;
                int row = v >> 4, u = v & 15;
                float4 f = pf[it];
                __nv_bfloat16 h0 = __float2bfloat16_rn(f.x), h1 = __float2bfloat16_rn(f.y);
                __nv_bfloat16 h2 = __float2bfloat16_rn(f.z), h3 = __float2bfloat16_rn(f.w);
                __nv_bfloat16 l0 = __float2bfloat16_rn(f.x - __bfloat162float(h0));
                __nv_bfloat16 l1 = __float2bfloat16_rn(f.y - __bfloat162float(h1));
                __nv_bfloat16 l2 = __float2bfloat16_rn(f.z - __bfloat162float(h2));
                __nv_bfloat16 l3 = __float2bfloat16_rn(f.w - __bfloat162float(h3));
                unsigned short s0, s1, s2, s3, q0, q1, q2, q3;
                memcpy(&s0, &h0, 2); memcpy(&s1, &h1, 2); memcpy(&s2, &h2, 2); memcpy(&s3, &h3, 2);
                memcpy(&q0, &l0, 2); memcpy(&q1, &l1, 2); memcpy(&q2, &l2, 2); memcpy(&q3, &l3, 2);
                uint32_t hx = (uint32_t)s0 | ((uint32_t)s1 << 16);
                uint32_t hy = (uint32_t)s2 | ((uint32_t)s3 << 16);
                uint32_t lx = (uint32_t)q0 | ((uint32_t)q1 << 16);
                uint32_t ly = (uint32_t)q2 | ((uint32_t)q3 << 16);
                uint32_t off = SW128((uint32_t)(row * 128 + u * 8));
                asm volatile("st.shared.v2.b32 [%0], {%1,%2};" :: "r"(ah + off), "r"(hx), "r"(hy) : "memory");
                asm volatile("st.shared.v2.b32 [%0], {%1,%2};" :: "r"(al + off), "r"(lx), "r"(ly) : "memory");
            }
        }
        __syncthreads();
    }

    // ---- epilogue: + bias, store ----
    const float* bias = reinterpret_cast<const float*>(smem + SM_BIAS);
#pragma unroll
    for (int mt = 0; mt < 2; mt++) {
        int row_lo = r0 + m0 + mt * 16 + (lane >> 2);
        int row_hi = row_lo + 8;
#pragma unroll
        for (int nt = 0; nt < 8; nt++) {
            int col = n0 + nt * 8 + (lane & 3) * 2;
            float2 b2 = *reinterpret_cast<const float2*>(bias + col);
            if (row_lo < N) {
                float2 o = make_float2(acc[mt][nt][0] + b2.x, acc[mt][nt][1] + b2.y);
                *reinterpret_cast<float2*>(out + (size_t)row_lo * DDIM + col) = o;
            }
            if (row_hi < N) {
                float2 o = make_float2(acc[mt][nt][2] + b2.x, acc[mt][nt][3] + b2.y);
                *reinterpret_cast<float2*>(out + (size_t)row_hi * DDIM + col) = o;
            }
        }
    }
}

// ---------------------------------------------------------------------------
extern "C" void kernel_launch(void* const* d_in, const int* in_sizes, int n_in,
                              void* d_out, int out_size)
{
    const float* v_in = (const float*)d_in[2];
    const float* Wv   = (const float*)d_in[7];
    const float* bv   = (const float*)d_in[8];
    float* out = (float*)d_out;

    const int N = in_sizes[0] / CIN;
    const int rowBlocks = (N + 127) / 128;

    cudaFuncSetAttribute(gemm_hmma, cudaFuncAttributeMaxDynamicSharedMemorySize, SMEM_SZ);

    reduce_weights<<<(DDIM * CIN + 255) / 256, 256>>>(Wv, bv);
    gemm_hmma<<<rowBlocks, 256, SMEM_SZ>>>(v_in, out, N);
}